// round 17
// baseline (speedup 1.0000x reference)
#include <cuda_runtime.h>
#include <cuda_fp16.h>
#include <cstdint>

// Problem constants
#define B_    8
#define IC_   16
#define H_    32
#define W_    32
#define OC_   32
#define TPO_  144               // tables per output channel
#define QTR_  36                // tables per warp (4-way split)
#define CHUNK_ 4                // fp16-accumulation chunk (36 = 9*4)

// Tiling: 8 output rows per block; tile element (c,kh,pw) = uint4 packing
// padded rows kh..kh+7 as 8 halves. Padded rows needed: oh0-1 .. oh0+8 (10).
#define ROWS_PER_BLK 8
#define PW_   36                // padded width (cols 0..33 used; 34,35 pad)
#define CQ_   (3 * PW_)         // uint4 elems per channel (kh = 0..2)
#define TILEQ (IC_ * CQ_)       // 1728 uint4 = 27648 B

// packed f32x2 helpers
__device__ __forceinline__ unsigned long long pack_f32x2(float lo, float hi) {
    unsigned long long r;
    asm("mov.b64 %0, {%1, %2};" : "=l"(r)
        : "r"(__float_as_uint(lo)), "r"(__float_as_uint(hi)));
    return r;
}
__device__ __forceinline__ void add_f32x2(unsigned long long& acc, unsigned long long v) {
    asm("add.rn.f32x2 %0, %1, %2;" : "=l"(acc) : "l"(acc), "l"(v));
}
__device__ __forceinline__ float2 unpack_f32x2(unsigned long long v) {
    unsigned lo, hi;
    asm("mov.b64 {%0, %1}, %2;" : "=r"(lo), "=r"(hi) : "l"(v));
    return make_float2(__uint_as_float(lo), __uint_as_float(hi));
}

// ---------------------------------------------------------------------------
// Fused kernel. grid = (4 row-tiles, 16 oc-pairs, 8 batch) = 512 blocks,
// 256 threads (8 warps). warp w -> oc = ogp*2 + (w&1), table quarter = w>>1&3.
// One LDS.128 per operand gather serves all 8 pixel rows of a thread.
// Per-table bilinear math in packed fp16 (HFMA2); chunk-of-4 fp16
// accumulation flushed into packed fp32 via add.rn.f32x2.
// ---------------------------------------------------------------------------
__global__ __launch_bounds__(256, 4)
void lut_conv_fused(const float* __restrict__ in,
                    const float* __restrict__ w_luts,
                    const int* __restrict__ mc,
                    const int* __restrict__ mkh,
                    const int* __restrict__ mkw,
                    float* __restrict__ out) {
    __shared__ uint4  s_q[TILEQ];               // 27648 B packed fp16 tile
    __shared__ uint4  s_rec[2 * TPO_ + 1];      //  4624 B (+1 zero pad rec)
    __shared__ float  s_a[2][TPO_];             //  1152 B constant terms
    __shared__ float  s_red[2][3][8][32];       //  6144 B partner accumulators

    const int tid = threadIdx.x;
    const int rt  = blockIdx.x;        // row tile 0..3
    const int ogp = blockIdx.y;        // oc pair 0..15
    const int b   = blockIdx.z;        // batch 0..7
    const int oh0 = rt * ROWS_PER_BLK;

    // ---- Phase 1a: stage tile. Threads 0..127: one (c, col-quad) each. ----
    if (tid < 128) {
        const int c = tid >> 3;
        const int q = tid & 7;               // float4 col group: iw = 4q..4q+3
        const float4* rowp = reinterpret_cast<const float4*>(
            in + ((size_t)b * IC_ + c) * H_ * W_) + q;
        float4 f[10];
        #pragma unroll
        for (int r = 0; r < 10; r++) {
            int ih = oh0 + r - 1;
            if ((unsigned)ih < (unsigned)H_) f[r] = rowp[ih * (W_ / 4)];
            else f[r] = make_float4(0.f, 0.f, 0.f, 0.f);
        }
        const float* ff = reinterpret_cast<const float*>(f);  // ff[r*4 + j]
        #pragma unroll
        for (int kh = 0; kh < 3; kh++) {
            #pragma unroll
            for (int j = 0; j < 4; j++) {
                __half2 p0 = __floats2half2_rn(ff[(kh + 0) * 4 + j], ff[(kh + 1) * 4 + j]);
                __half2 p1 = __floats2half2_rn(ff[(kh + 2) * 4 + j], ff[(kh + 3) * 4 + j]);
                __half2 p2 = __floats2half2_rn(ff[(kh + 4) * 4 + j], ff[(kh + 5) * 4 + j]);
                __half2 p3 = __floats2half2_rn(ff[(kh + 6) * 4 + j], ff[(kh + 7) * 4 + j]);
                uint4 v;
                v.x = *reinterpret_cast<unsigned*>(&p0);
                v.y = *reinterpret_cast<unsigned*>(&p1);
                v.z = *reinterpret_cast<unsigned*>(&p2);
                v.w = *reinterpret_cast<unsigned*>(&p3);
                s_q[(c * 3 + kh) * PW_ + 4 * q + 1 + j] = v;
            }
        }
    } else {
        // Threads 128..255: zero border columns pw=0 and pw=33.
        int t2 = tid - 128;
        if (t2 < 96) {
            int c   = t2 / 6;
            int rem = t2 - c * 6;
            int kh  = rem >> 1;
            int pw  = (rem & 1) ? 33 : 0;
            s_q[(c * 3 + kh) * PW_ + pw] = make_uint4(0u, 0u, 0u, 0u);
        }
    }

    // ---- Phase 1b: table records for this oc pair (288 of them) ----
    for (int j = tid; j < 2 * TPO_; j += 256) {
        int ocg = j / TPO_;
        int r   = j - ocg * TPO_;
        int t   = (ogp * 2 + ocg) * TPO_ + r;
        float4 w = __ldg(reinterpret_cast<const float4*>(w_luts) + t);
        float bb = 0.25f * (-w.x + w.y - w.z + w.w);
        float cc = 0.25f * (-w.x - w.y + w.z + w.w);
        float dd = 0.25f * ( w.x - w.y - w.z + w.w);
        s_a[ocg][r] = 0.25f * ((w.x + w.y) + (w.z + w.w));
        int m0 = 2 * t, m1 = 2 * t + 1;
        // byte offsets of uint4 element (c,kh,kw); lane adds lane*16.
        // max = ((15*3+2)*36 + 2)*16 + 31*16 = 27600 < 65536 -> 16-bit pack ok
        unsigned off0 = (unsigned)(((mc[m0] * 3 + mkh[m0]) * PW_ + mkw[m0]) * 16);
        unsigned off1 = (unsigned)(((mc[m1] * 3 + mkh[m1]) * PW_ + mkw[m1]) * 16);
        __half2 b2 = __float2half2_rn(bb);
        __half2 c2 = __float2half2_rn(cc);
        __half2 d2 = __float2half2_rn(dd);
        uint4 rec;
        rec.x = *reinterpret_cast<unsigned*>(&b2);
        rec.y = *reinterpret_cast<unsigned*>(&c2);
        rec.z = *reinterpret_cast<unsigned*>(&d2);
        rec.w = off0 | (off1 << 16);
        s_rec[j] = rec;
    }
    if (tid == 0) s_rec[2 * TPO_] = make_uint4(0u, 0u, 0u, 0u);
    __syncthreads();

    // ---- Phase 2: main loop (36 iters per warp, 9 chunks of 4) ----
    const int lane = tid & 31;
    const int warp = tid >> 5;
    const int ocg  = warp & 1;         // oc within pair
    const int qtr  = warp >> 1;        // table quarter 0..3
    const int oc   = ogp * 2 + ocg;

    const uint4* __restrict__ recp = s_rec + ocg * TPO_ + qtr * QTR_;
    const char*  __restrict__ spb  = reinterpret_cast<const char*>(s_q) + lane * 16;

    unsigned long long acc01 = 0ull;   // packed fp32: rows 0,1
    unsigned long long acc23 = 0ull;   // rows 2,3
    unsigned long long acc45 = 0ull;   // rows 4,5
    unsigned long long acc67 = 0ull;   // rows 6,7

    // 2-stage software pipeline; final prefetch reads a valid pad record.
    uint4 rc = recp[0];
    uint4 q0 = *reinterpret_cast<const uint4*>(spb + (rc.w & 0xFFFFu));
    uint4 q1 = *reinterpret_cast<const uint4*>(spb + (rc.w >> 16));

    for (int ch = 0; ch < QTR_ / CHUNK_; ch++) {
        __half2 h01 = __half2half2(__ushort_as_half(0));
        __half2 h23 = h01, h45 = h01, h67 = h01;

        #pragma unroll
        for (int i = 0; i < CHUNK_; i++) {
            uint4 rcc = rc;
            uint4 a0  = q0;
            uint4 a1  = q1;
            rc = recp[ch * CHUNK_ + i + 1];
            q0 = *reinterpret_cast<const uint4*>(spb + (rc.w & 0xFFFFu));
            q1 = *reinterpret_cast<const uint4*>(spb + (rc.w >> 16));

            __half2 b2 = *reinterpret_cast<__half2*>(&rcc.x);
            __half2 c2 = *reinterpret_cast<__half2*>(&rcc.y);
            __half2 d2 = *reinterpret_cast<__half2*>(&rcc.z);

            // v = c*x1 + x0*(b + d*x1) per row-pair; 4 row-pairs
            {
                __half2 x0 = *reinterpret_cast<__half2*>(&a0.x);
                __half2 x1 = *reinterpret_cast<__half2*>(&a1.x);
                __half2 t  = __hfma2(d2, x1, b2);
                h01 = __hadd2(h01, __hfma2(c2, x1, __hmul2(x0, t)));
            }
            {
                __half2 x0 = *reinterpret_cast<__half2*>(&a0.y);
                __half2 x1 = *reinterpret_cast<__half2*>(&a1.y);
                __half2 t  = __hfma2(d2, x1, b2);
                h23 = __hadd2(h23, __hfma2(c2, x1, __hmul2(x0, t)));
            }
            {
                __half2 x0 = *reinterpret_cast<__half2*>(&a0.z);
                __half2 x1 = *reinterpret_cast<__half2*>(&a1.z);
                __half2 t  = __hfma2(d2, x1, b2);
                h45 = __hadd2(h45, __hfma2(c2, x1, __hmul2(x0, t)));
            }
            {
                __half2 x0 = *reinterpret_cast<__half2*>(&a0.w);
                __half2 x1 = *reinterpret_cast<__half2*>(&a1.w);
                __half2 t  = __hfma2(d2, x1, b2);
                h67 = __hadd2(h67, __hfma2(c2, x1, __hmul2(x0, t)));
            }
        }

        // flush chunk to packed fp32 accumulators
        float2 f01 = __half22float2(h01);
        float2 f23 = __half22float2(h23);
        float2 f45 = __half22float2(h45);
        float2 f67 = __half22float2(h67);
        add_f32x2(acc01, pack_f32x2(f01.x, f01.y));
        add_f32x2(acc23, pack_f32x2(f23.x, f23.y));
        add_f32x2(acc45, pack_f32x2(f45.x, f45.y));
        add_f32x2(acc67, pack_f32x2(f67.x, f67.y));
    }

    float2 r01 = unpack_f32x2(acc01);
    float2 r23 = unpack_f32x2(acc23);
    float2 r45 = unpack_f32x2(acc45);
    float2 r67 = unpack_f32x2(acc67);
    float acc[8] = { r01.x, r01.y, r23.x, r23.y, r45.x, r45.y, r67.x, r67.y };

    // ---- Phase 3: 4-way reduction + constant term, store ----
    if (qtr != 0) {
        #pragma unroll
        for (int p = 0; p < 8; p++)
            s_red[ocg][qtr - 1][p][lane] = acc[p];
    }
    __syncthreads();
    if (qtr == 0) {
        // deterministic per-oc constant-term reduction (144 fp32 values)
        float s = 0.f;
        #pragma unroll
        for (int r = lane; r < TPO_; r += 32) s += s_a[ocg][r];
        #pragma unroll
        for (int o = 16; o >= 1; o >>= 1)
            s += __shfl_xor_sync(0xFFFFFFFFu, s, o);

        float* ob = out + (((size_t)b * OC_ + oc) * H_ + oh0) * W_ + lane;
        #pragma unroll
        for (int p = 0; p < 8; p++) {
            float v = acc[p] + s;
            v += s_red[ocg][0][p][lane];
            v += s_red[ocg][1][p][lane];
            v += s_red[ocg][2][p][lane];
            ob[p * W_] = v;
        }
    }
}

// ---------------------------------------------------------------------------
extern "C" void kernel_launch(void* const* d_in, const int* in_sizes, int n_in,
                              void* d_out, int out_size) {
    const float* input  = (const float*)d_in[0];   // (8,16,32,32)
    const float* w_luts = (const float*)d_in[1];   // (4608,4)
    const int*   mc     = (const int*)d_in[2];     // (9216,)
    const int*   mkh    = (const int*)d_in[3];     // (9216,)
    const int*   mkw    = (const int*)d_in[4];     // (9216,)
    float*       out    = (float*)d_out;           // (8,32,32,32)

    dim3 grid(H_ / ROWS_PER_BLK, OC_ / 2, B_);     // (4, 16, 8)
    lut_conv_fused<<<grid, 256>>>(input, w_luts, mc, mkh, mkw, out);
}